// round 2
// baseline (speedup 1.0000x reference)
#include <cuda_runtime.h>
#include <cuda_bf16.h>
#include <math.h>

#define MAX_N 100000
#define MAX_E 3200000

// ---- scratch (static __device__ globals; allocation-free) ----
__device__ int   g_deg[MAX_N + 1];
__device__ int   g_off[MAX_N + 1];
__device__ int   g_wp[MAX_N];
__device__ int   g_csr[MAX_E];
__device__ int   g_bsum[128];
__device__ int   g_bbase[128];
__device__ float g_y0[MAX_N * 32];   // padded feature rows: 32 floats = one 128B line
__device__ float g_y1[MAX_N * 32];

// ---------------- CSR build ----------------

__global__ void k_zero(int n) {
    int i = blockIdx.x * blockDim.x + threadIdx.x;
    if (i < n) g_deg[i] = 0;
}

__global__ void k_count(const int* __restrict__ ei, int E, int n) {
    int i = blockIdx.x * blockDim.x + threadIdx.x;
    if (i < E) {
        int d = ei[E + i];
        if ((unsigned)d < (unsigned)n) atomicAdd(&g_deg[d], 1);
    }
}

__global__ void k_scan1(int n) {
    __shared__ int s[1024];
    int t = threadIdx.x;
    int i = blockIdx.x * 1024 + t;
    int v = (i < n) ? g_deg[i] : 0;
    s[t] = v;
    __syncthreads();
    #pragma unroll
    for (int d = 1; d < 1024; d <<= 1) {
        int a = (t >= d) ? s[t - d] : 0;
        __syncthreads();
        s[t] += a;
        __syncthreads();
    }
    if (i < n) g_off[i] = s[t] - v;              // exclusive within block
    if (t == 1023) g_bsum[blockIdx.x] = s[t];    // block total
}

__global__ void k_scan2(int nb, int n) {
    __shared__ int s[128];
    int t = threadIdx.x;
    if (t < nb) s[t] = g_bsum[t];
    __syncthreads();
    if (t == 0) {
        int run = 0;
        for (int b = 0; b < nb; b++) { g_bbase[b] = run; run += s[b]; }
        g_off[n] = run;
    }
}

__global__ void k_scan3(int n) {
    int i = blockIdx.x * blockDim.x + threadIdx.x;
    if (i < n) {
        int o = g_off[i] + g_bbase[i >> 10];
        g_off[i] = o;
        g_wp[i] = o;
    }
}

__global__ void k_fill(const int* __restrict__ ei, int E, int n) {
    int i = blockIdx.x * blockDim.x + threadIdx.x;
    if (i < E) {
        int s = ei[i];
        int d = ei[E + i];
        if ((unsigned)d < (unsigned)n && (unsigned)s < (unsigned)n) {
            int p = atomicAdd(&g_wp[d], 1);
            g_csr[p] = s;
        }
    }
}

// ---------------- layer 1 pre-GEMM: y0 = x @ w1a  (128 -> 30, padded to 32) ----------------

__global__ void k_pre(const float* __restrict__ x, const float* __restrict__ w, int n) {
    __shared__ float ws[128 * 30];
    __shared__ float xs[8 * 128];
    int tid = threadIdx.x;
    for (int i = tid; i < 128 * 30; i += 256) ws[i] = w[i];
    int n0 = blockIdx.x * 8;
    for (int i = tid; i < 8 * 128; i += 256) {
        int node = n0 + (i >> 7);
        xs[i] = (node < n) ? x[node * 128 + (i & 127)] : 0.f;
    }
    __syncthreads();
    if (tid < 240) {
        int ln = tid / 30, c = tid % 30;
        int node = n0 + ln;
        if (node < n) {
            float acc = 0.f;
            #pragma unroll 16
            for (int k = 0; k < 128; k++) acc += xs[ln * 128 + k] * ws[k * 30 + c];
            g_y0[node * 32 + c] = acc;
        }
    } else {
        int idx = tid - 240;
        int node = n0 + (idx >> 1);
        if (node < n) g_y0[node * 32 + 30 + (idx & 1)] = 0.f;
    }
}

// ---------------- fused layer: CSR aggregate + bias/relu + (30x30)@wb + bias/relu
//                  then either next pre-GEMM (30x30)@wa_next or log_softmax ----------------

__global__ void k_layer(int dir, int finalLayer,
                        const float* __restrict__ ba, const float* __restrict__ wb,
                        const float* __restrict__ bb, const float* __restrict__ wa,
                        float* __restrict__ out, int n) {
    __shared__ float s_wb[900];
    __shared__ float s_wa[900];
    __shared__ float s_ba[32];
    __shared__ float s_bb[32];
    __shared__ float s_t[8][32];
    __shared__ float s_h[8][32];

    const float* __restrict__ yin  = dir ? g_y1 : g_y0;
    float* __restrict__       yout = dir ? g_y0 : g_y1;

    int tid = threadIdx.x;
    for (int i = tid; i < 900; i += 256) {
        s_wb[i] = wb[i];
        if (!finalLayer) s_wa[i] = wa[i];
    }
    if (tid < 32) {
        s_ba[tid] = (tid < 30) ? ba[tid] : 0.f;
        s_bb[tid] = (tid < 30) ? bb[tid] : 0.f;
    }
    __syncthreads();

    int wid = tid >> 5, lane = tid & 31;
    int node = blockIdx.x * 8 + wid;
    if (node >= n) return;

    int se = 0;
    if (lane < 2) se = g_off[node + lane];
    int start = __shfl_sync(0xffffffffu, se, 0);
    int end   = __shfl_sync(0xffffffffu, se, 1);

    // self term (+ padded lanes read zeros)
    float a0 = yin[node * 32 + lane], a1 = 0.f, a2 = 0.f, a3 = 0.f;

    for (int e = start; e < end; e += 32) {
        int m = end - e;
        int s = (lane < m) ? g_csr[e + lane] : -1;
        #pragma unroll
        for (int j = 0; j < 32; j += 4) {
            int i0 = __shfl_sync(0xffffffffu, s, j);
            int i1 = __shfl_sync(0xffffffffu, s, j + 1);
            int i2 = __shfl_sync(0xffffffffu, s, j + 2);
            int i3 = __shfl_sync(0xffffffffu, s, j + 3);
            if (i0 >= 0) a0 += yin[i0 * 32 + lane];
            if (i1 >= 0) a1 += yin[i1 * 32 + lane];
            if (i2 >= 0) a2 += yin[i2 * 32 + lane];
            if (i3 >= 0) a3 += yin[i3 * 32 + lane];
        }
    }

    float t = fmaxf((a0 + a1) + (a2 + a3) + s_ba[lane], 0.f);
    if (lane >= 30) t = 0.f;
    s_t[wid][lane] = t;
    __syncwarp();

    float h = 0.f;
    if (lane < 30) {
        float z = s_bb[lane];
        #pragma unroll
        for (int k = 0; k < 30; k++) z += s_t[wid][k] * s_wb[k * 30 + lane];
        h = fmaxf(z, 0.f);
    }

    if (finalLayer) {
        float hv = (lane < 30) ? h : -1e30f;
        float mx = hv;
        #pragma unroll
        for (int o = 16; o > 0; o >>= 1) mx = fmaxf(mx, __shfl_xor_sync(0xffffffffu, mx, o));
        float ex = (lane < 30) ? expf(h - mx) : 0.f;
        float sm = ex;
        #pragma unroll
        for (int o = 16; o > 0; o >>= 1) sm += __shfl_xor_sync(0xffffffffu, sm, o);
        if (lane < 30) out[node * 30 + lane] = h - mx - logf(sm);
    } else {
        s_h[wid][lane] = h;
        __syncwarp();
        float yv = 0.f;
        if (lane < 30) {
            #pragma unroll
            for (int k = 0; k < 30; k++) yv += s_h[wid][k] * s_wa[k * 30 + lane];
        }
        yout[node * 32 + lane] = yv;   // lanes 30/31 write 0 padding
    }
}

// ---------------- launch ----------------

extern "C" void kernel_launch(void* const* d_in, const int* in_sizes, int n_in,
                              void* d_out, int out_size) {
    const float* x   = (const float*)d_in[0];
    const int*   ei  = (const int*)d_in[1];
    const float* w1a = (const float*)d_in[2];
    const float* b1a = (const float*)d_in[3];
    const float* w1b = (const float*)d_in[4];
    const float* b1b = (const float*)d_in[5];
    const float* w2a = (const float*)d_in[6];
    const float* b2a = (const float*)d_in[7];
    const float* w2b = (const float*)d_in[8];
    const float* b2b = (const float*)d_in[9];
    const float* w3a = (const float*)d_in[10];
    const float* b3a = (const float*)d_in[11];
    const float* w3b = (const float*)d_in[12];
    const float* b3b = (const float*)d_in[13];
    float* out = (float*)d_out;

    int n = in_sizes[0] / 128;
    int E = in_sizes[1] / 2;

    int eb   = (E + 255) / 256;
    int nb1k = (n + 1023) / 1024;
    int nb   = (n + 255) / 256;
    int nwb  = (n + 7) / 8;

    k_zero <<<nb1k, 1024>>>(n);
    k_count<<<eb, 256>>>(ei, E, n);
    k_scan1<<<nb1k, 1024>>>(n);
    k_scan2<<<1, 128>>>(nb1k, n);
    k_scan3<<<nb, 256>>>(n);
    k_fill <<<eb, 256>>>(ei, E, n);

    k_pre  <<<nwb, 256>>>(x, w1a, n);
    k_layer<<<nwb, 256>>>(0, 0, b1a, w1b, b1b, w2a, nullptr, n);
    k_layer<<<nwb, 256>>>(1, 0, b2a, w2b, b2b, w3a, nullptr, n);
    k_layer<<<nwb, 256>>>(0, 1, b3a, w3b, b3b, nullptr, out, n);
}

// round 3
// speedup vs baseline: 1.0667x; 1.0667x over previous
#include <cuda_runtime.h>
#include <cuda_bf16.h>
#include <math.h>

#define MAX_N 100000
#define MAX_E 3200000

// ---- scratch (static __device__ globals; allocation-free) ----
__device__ int   g_deg[MAX_N + 1];
__device__ int   g_off[MAX_N + 1];
__device__ int   g_wp[MAX_N];
__device__ int   g_csr[MAX_E];
__device__ int   g_total;
__device__ float g_y0[MAX_N * 32];   // padded rows: 32 floats = one 128B line
__device__ float g_y1[MAX_N * 32];

// ---------------- CSR build ----------------

__global__ void k_zero(int n) {
    int i = blockIdx.x * blockDim.x + threadIdx.x;
    if (i < n) g_deg[i] = 0;
    if (i == 0) g_total = 0;
}

__global__ void k_count(const int* __restrict__ ei, int E, int n) {
    int i = blockIdx.x * blockDim.x + threadIdx.x;
    if (i < E) {
        int d = ei[E + i];
        if ((unsigned)d < (unsigned)n) atomicAdd(&g_deg[d], 1);
    }
}

// block scan of degrees + atomic block-base allocation (one kernel replaces 3)
__global__ void k_alloc(int n) {
    __shared__ int s[1024];
    __shared__ int base;
    int t = threadIdx.x;
    int i = blockIdx.x * 1024 + t;
    int v = (i < n) ? g_deg[i] : 0;
    s[t] = v;
    __syncthreads();
    #pragma unroll
    for (int d = 1; d < 1024; d <<= 1) {
        int a = (t >= d) ? s[t - d] : 0;
        __syncthreads();
        s[t] += a;
        __syncthreads();
    }
    if (t == 1023) base = atomicAdd(&g_total, s[1023]);
    __syncthreads();
    if (i < n) {
        int o = s[t] - v + base;
        g_off[i] = o;
        g_wp[i] = o;
    }
}

__global__ void k_fill(const int* __restrict__ ei, int E, int n) {
    int i = blockIdx.x * blockDim.x + threadIdx.x;
    if (i < E) {
        int s = ei[i];
        int d = ei[E + i];
        if ((unsigned)d < (unsigned)n && (unsigned)s < (unsigned)n) {
            int p = atomicAdd(&g_wp[d], 1);
            g_csr[p] = s;
        }
    }
}

// ---------------- layer-1 pre-GEMM: y0 = x @ w1a  (128 -> 30, padded to 32) ----------------
// 32 nodes per block; thread = (node_local = tid>>3, cg = tid&7) computes 4 channels.

__global__ void k_pre(const float* __restrict__ x, const float* __restrict__ w, int n) {
    __shared__ float  xs[32 * 132];   // padded rows: conflict-free for 4 node-groups/warp
    __shared__ float4 ws4[128 * 8];   // ws4[k*8+cg] = w[k][cg*4 .. cg*4+3] (0-padded)
    int tid = threadIdx.x;
    int n0 = blockIdx.x * 32;

    for (int idx = tid; idx < 1024; idx += 256) {
        int k = idx >> 3, cg = idx & 7, c0 = cg * 4;
        float4 v;
        v.x = (c0 + 0 < 30) ? w[k * 30 + c0 + 0] : 0.f;
        v.y = (c0 + 1 < 30) ? w[k * 30 + c0 + 1] : 0.f;
        v.z = (c0 + 2 < 30) ? w[k * 30 + c0 + 2] : 0.f;
        v.w = (c0 + 3 < 30) ? w[k * 30 + c0 + 3] : 0.f;
        ws4[idx] = v;
    }
    const float4* x4 = (const float4*)x;
    for (int idx = tid; idx < 1024; idx += 256) {
        int nl = idx >> 5, ii = idx & 31;
        int node = n0 + nl;
        float4 xv = make_float4(0.f, 0.f, 0.f, 0.f);
        if (node < n) xv = x4[node * 32 + ii];
        *(float4*)&xs[nl * 132 + ii * 4] = xv;
    }
    __syncthreads();

    int nl = tid >> 3, cg = tid & 7;
    int node = n0 + nl;
    float4 acc = make_float4(0.f, 0.f, 0.f, 0.f);
    #pragma unroll 8
    for (int k = 0; k < 128; k++) {
        float  xv = xs[nl * 132 + k];
        float4 wv = ws4[k * 8 + cg];
        acc.x += xv * wv.x; acc.y += xv * wv.y;
        acc.z += xv * wv.z; acc.w += xv * wv.w;
    }
    if (node < n) {
        if (cg == 7) { acc.z = 0.f; acc.w = 0.f; }  // channels 30,31 padding
        ((float4*)g_y0)[node * 8 + cg] = acc;
    }
}

// ---------------- fused layer (persistent): CSR aggregate (float4, 4 edges/warp-LDG)
//                  + bias/relu + (30x30)@wb + bias/relu, then next (30x30)@wa or log_softmax

__global__ void k_layer(int dir, int finalLayer,
                        const float* __restrict__ ba, const float* __restrict__ wb,
                        const float* __restrict__ bb, const float* __restrict__ wa,
                        float* __restrict__ out, int n) {
    __shared__ float s_wb[900];
    __shared__ float s_wa[900];
    __shared__ float s_ba[32];
    __shared__ float s_bb[32];
    __shared__ float s_t[8][32];
    __shared__ float s_h[8][32];

    const float4* __restrict__ yin4 = (const float4*)(dir ? g_y1 : g_y0);
    float* __restrict__        yout = dir ? g_y0 : g_y1;

    int tid = threadIdx.x;
    for (int i = tid; i < 900; i += 256) {
        s_wb[i] = wb[i];
        if (!finalLayer) s_wa[i] = wa[i];
    }
    if (tid < 32) {
        s_ba[tid] = (tid < 30) ? ba[tid] : 0.f;
        s_bb[tid] = (tid < 30) ? bb[tid] : 0.f;
    }
    __syncthreads();

    int wid = tid >> 5, lane = tid & 31;
    int sub = lane & 7, g = lane >> 3;
    int nstride = gridDim.x * 8;

    for (int node = blockIdx.x * 8 + wid; node < n; node += nstride) {
        int start = 0, deg = 0;
        if (lane == 0) { start = g_off[node]; deg = g_deg[node]; }
        start = __shfl_sync(0xffffffffu, start, 0);
        deg   = __shfl_sync(0xffffffffu, deg, 0);
        int end = start + deg;

        float4 acc = make_float4(0.f, 0.f, 0.f, 0.f);
        if (g == 0) acc = yin4[node * 8 + sub];   // self term (counted once)

        for (int e = start; e < end; e += 32) {
            int m = end - e;
            int s = (lane < m) ? g_csr[e + lane] : -1;
            #pragma unroll
            for (int j = 0; j < 8; j++) {
                int idx = __shfl_sync(0xffffffffu, s, j * 4 + g);
                if (idx >= 0) {
                    float4 v = yin4[idx * 8 + sub];
                    acc.x += v.x; acc.y += v.y; acc.z += v.z; acc.w += v.w;
                }
            }
        }
        // combine the 4 lane-groups
        #pragma unroll
        for (int off = 8; off <= 16; off <<= 1) {
            acc.x += __shfl_xor_sync(0xffffffffu, acc.x, off);
            acc.y += __shfl_xor_sync(0xffffffffu, acc.y, off);
            acc.z += __shfl_xor_sync(0xffffffffu, acc.z, off);
            acc.w += __shfl_xor_sync(0xffffffffu, acc.w, off);
        }
        if (g == 0) {
            int c0 = sub * 4;
            float4 t;
            t.x = fmaxf(acc.x + s_ba[c0 + 0], 0.f);
            t.y = fmaxf(acc.y + s_ba[c0 + 1], 0.f);
            t.z = fmaxf(acc.z + s_ba[c0 + 2], 0.f);
            t.w = fmaxf(acc.w + s_ba[c0 + 3], 0.f);
            if (sub == 7) { t.z = 0.f; t.w = 0.f; }
            *(float4*)&s_t[wid][c0] = t;
        }
        __syncwarp();

        float h = 0.f;
        if (lane < 30) {
            float z = s_bb[lane];
            #pragma unroll
            for (int k = 0; k < 30; k++) z += s_t[wid][k] * s_wb[k * 30 + lane];
            h = fmaxf(z, 0.f);
        }

        if (finalLayer) {
            float hv = (lane < 30) ? h : -1e30f;
            float mx = hv;
            #pragma unroll
            for (int o = 16; o > 0; o >>= 1) mx = fmaxf(mx, __shfl_xor_sync(0xffffffffu, mx, o));
            float ex = (lane < 30) ? expf(h - mx) : 0.f;
            float sm = ex;
            #pragma unroll
            for (int o = 16; o > 0; o >>= 1) sm += __shfl_xor_sync(0xffffffffu, sm, o);
            if (lane < 30) out[node * 30 + lane] = h - mx - logf(sm);
        } else {
            s_h[wid][lane] = (lane < 30) ? h : 0.f;
            __syncwarp();
            float yv = 0.f;
            if (lane < 30) {
                #pragma unroll
                for (int k = 0; k < 30; k++) yv += s_h[wid][k] * s_wa[k * 30 + lane];
            }
            yout[node * 32 + lane] = yv;   // lanes 30/31 write 0 padding
        }
        __syncwarp();   // protect s_t/s_h before next grid-stride iteration
    }
}

// ---------------- launch ----------------

extern "C" void kernel_launch(void* const* d_in, const int* in_sizes, int n_in,
                              void* d_out, int out_size) {
    const float* x   = (const float*)d_in[0];
    const int*   ei  = (const int*)d_in[1];
    const float* w1a = (const float*)d_in[2];
    const float* b1a = (const float*)d_in[3];
    const float* w1b = (const float*)d_in[4];
    const float* b1b = (const float*)d_in[5];
    const float* w2a = (const float*)d_in[6];
    const float* b2a = (const float*)d_in[7];
    const float* w2b = (const float*)d_in[8];
    const float* b2b = (const float*)d_in[9];
    const float* w3a = (const float*)d_in[10];
    const float* b3a = (const float*)d_in[11];
    const float* w3b = (const float*)d_in[12];
    const float* b3b = (const float*)d_in[13];
    float* out = (float*)d_out;

    int n = in_sizes[0] / 128;
    int E = in_sizes[1] / 2;

    int eb   = (E + 255) / 256;
    int nb1k = (n + 1023) / 1024;
    int nwb  = (n + 7) / 8;
    int lgrid = nwb < 1184 ? nwb : 1184;

    k_zero <<<nb1k, 1024>>>(n);
    k_count<<<eb, 256>>>(ei, E, n);
    k_alloc<<<nb1k, 1024>>>(n);
    k_fill <<<eb, 256>>>(ei, E, n);

    k_pre  <<<(n + 31) / 32, 256>>>(x, w1a, n);
    k_layer<<<lgrid, 256>>>(0, 0, b1a, w1b, b1b, w2a, nullptr, n);
    k_layer<<<lgrid, 256>>>(1, 0, b2a, w2b, b2b, w3a, nullptr, n);
    k_layer<<<lgrid, 256>>>(0, 1, b3a, w3b, b3b, nullptr, out, n);
}

// round 4
// speedup vs baseline: 1.0773x; 1.0100x over previous
#include <cuda_runtime.h>
#include <cuda_bf16.h>
#include <math.h>

#define MAX_N 100000
#define MAX_E 3200000

// ---- scratch (static __device__ globals; allocation-free) ----
__device__ int   g_deg[MAX_N + 1];
__device__ int   g_off[MAX_N + 1];
__device__ int   g_wp[MAX_N];
__device__ int   g_csr[MAX_E];
__device__ int   g_total;
__device__ float g_y0[MAX_N * 32];   // padded rows: 32 floats = one 128B line
__device__ float g_y1[MAX_N * 32];

// ---------------- CSR build ----------------

__global__ void k_zero(int n) {
    int i = blockIdx.x * blockDim.x + threadIdx.x;
    if (i < n) g_deg[i] = 0;
    if (i == 0) g_total = 0;
}

__global__ void k_count(const int* __restrict__ ei, int E, int n) {
    int i = blockIdx.x * blockDim.x + threadIdx.x;
    if (i < E) {
        int d = ei[E + i];
        if ((unsigned)d < (unsigned)n) atomicAdd(&g_deg[d], 1);
    }
}

// block scan of degrees + atomic block-base allocation (one kernel replaces 3)
__global__ void k_alloc(int n) {
    __shared__ int s[1024];
    __shared__ int base;
    int t = threadIdx.x;
    int i = blockIdx.x * 1024 + t;
    int v = (i < n) ? g_deg[i] : 0;
    s[t] = v;
    __syncthreads();
    #pragma unroll
    for (int d = 1; d < 1024; d <<= 1) {
        int a = (t >= d) ? s[t - d] : 0;
        __syncthreads();
        s[t] += a;
        __syncthreads();
    }
    if (t == 1023) base = atomicAdd(&g_total, s[1023]);
    __syncthreads();
    if (i < n) {
        int o = s[t] - v + base;
        g_off[i] = o;
        g_wp[i] = o;
    }
}

__global__ void k_fill(const int* __restrict__ ei, int E, int n) {
    int i = blockIdx.x * blockDim.x + threadIdx.x;
    if (i < E) {
        int s = ei[i];
        int d = ei[E + i];
        if ((unsigned)d < (unsigned)n && (unsigned)s < (unsigned)n) {
            int p = atomicAdd(&g_wp[d], 1);
            g_csr[p] = s;
        }
    }
}

// ---------------- layer-1 pre-GEMM: y0 = x @ w1a  (128 -> 30, padded to 32) ----------------
// 32 nodes per block; thread = (node_local = tid>>3, cg = tid&7) computes 4 channels.

__global__ void k_pre(const float* __restrict__ x, const float* __restrict__ w, int n) {
    __shared__ float  xs[32 * 132];   // padded rows: conflict-free for 4 node-groups/warp
    __shared__ float4 ws4[128 * 8];   // ws4[k*8+cg] = w[k][cg*4 .. cg*4+3] (0-padded)
    int tid = threadIdx.x;
    int n0 = blockIdx.x * 32;

    for (int idx = tid; idx < 1024; idx += 256) {
        int k = idx >> 3, cg = idx & 7, c0 = cg * 4;
        float4 v;
        v.x = (c0 + 0 < 30) ? w[k * 30 + c0 + 0] : 0.f;
        v.y = (c0 + 1 < 30) ? w[k * 30 + c0 + 1] : 0.f;
        v.z = (c0 + 2 < 30) ? w[k * 30 + c0 + 2] : 0.f;
        v.w = (c0 + 3 < 30) ? w[k * 30 + c0 + 3] : 0.f;
        ws4[idx] = v;
    }
    const float4* x4 = (const float4*)x;
    for (int idx = tid; idx < 1024; idx += 256) {
        int nl = idx >> 5, ii = idx & 31;
        int node = n0 + nl;
        float4 xv = make_float4(0.f, 0.f, 0.f, 0.f);
        if (node < n) xv = x4[node * 32 + ii];
        *(float4*)&xs[nl * 132 + ii * 4] = xv;
    }
    __syncthreads();

    int nl = tid >> 3, cg = tid & 7;
    int node = n0 + nl;
    float4 acc = make_float4(0.f, 0.f, 0.f, 0.f);
    #pragma unroll 8
    for (int k = 0; k < 128; k++) {
        float  xv = xs[nl * 132 + k];
        float4 wv = ws4[k * 8 + cg];
        acc.x += xv * wv.x; acc.y += xv * wv.y;
        acc.z += xv * wv.z; acc.w += xv * wv.w;
    }
    if (node < n) {
        if (cg == 7) { acc.z = 0.f; acc.w = 0.f; }  // channels 30,31 padding
        ((float4*)g_y0)[node * 8 + cg] = acc;
    }
}

// ---------------- fused layer (persistent): CSR aggregate (float4, 4 edges/warp-LDG)
//                  + bias/relu + (30x30)@wb + bias/relu, then next (30x30)@wa or log_softmax

__global__ void k_layer(int dir, int finalLayer,
                        const float* __restrict__ ba, const float* __restrict__ wb,
                        const float* __restrict__ bb, const float* __restrict__ wa,
                        float* __restrict__ out, int n) {
    __shared__ float s_wb[900];
    __shared__ float s_wa[900];
    __shared__ float s_ba[32];
    __shared__ float s_bb[32];
    __shared__ float s_t[8][32];
    __shared__ float s_h[8][32];

    const float4* __restrict__ yin4 = (const float4*)(dir ? g_y1 : g_y0);
    float* __restrict__        yout = dir ? g_y0 : g_y1;

    int tid = threadIdx.x;
    for (int i = tid; i < 900; i += 256) {
        s_wb[i] = wb[i];
        if (!finalLayer) s_wa[i] = wa[i];
    }
    if (tid < 32) {
        s_ba[tid] = (tid < 30) ? ba[tid] : 0.f;
        s_bb[tid] = (tid < 30) ? bb[tid] : 0.f;
    }
    __syncthreads();

    int wid = tid >> 5, lane = tid & 31;
    int sub = lane & 7, g = lane >> 3;
    int nstride = gridDim.x * 8;

    for (int node = blockIdx.x * 8 + wid; node < n; node += nstride) {
        int start = 0, deg = 0;
        if (lane == 0) { start = g_off[node]; deg = g_deg[node]; }
        start = __shfl_sync(0xffffffffu, start, 0);
        deg   = __shfl_sync(0xffffffffu, deg, 0);
        int end = start + deg;

        float4 acc = make_float4(0.f, 0.f, 0.f, 0.f);
        if (g == 0) acc = yin4[node * 8 + sub];   // self term (counted once)

        for (int e = start; e < end; e += 32) {
            int m = end - e;
            int s = (lane < m) ? g_csr[e + lane] : -1;
            #pragma unroll
            for (int j = 0; j < 8; j++) {
                int idx = __shfl_sync(0xffffffffu, s, j * 4 + g);
                if (idx >= 0) {
                    float4 v = yin4[idx * 8 + sub];
                    acc.x += v.x; acc.y += v.y; acc.z += v.z; acc.w += v.w;
                }
            }
        }
        // combine the 4 lane-groups
        #pragma unroll
        for (int off = 8; off <= 16; off <<= 1) {
            acc.x += __shfl_xor_sync(0xffffffffu, acc.x, off);
            acc.y += __shfl_xor_sync(0xffffffffu, acc.y, off);
            acc.z += __shfl_xor_sync(0xffffffffu, acc.z, off);
            acc.w += __shfl_xor_sync(0xffffffffu, acc.w, off);
        }
        if (g == 0) {
            int c0 = sub * 4;
            float4 t;
            t.x = fmaxf(acc.x + s_ba[c0 + 0], 0.f);
            t.y = fmaxf(acc.y + s_ba[c0 + 1], 0.f);
            t.z = fmaxf(acc.z + s_ba[c0 + 2], 0.f);
            t.w = fmaxf(acc.w + s_ba[c0 + 3], 0.f);
            if (sub == 7) { t.z = 0.f; t.w = 0.f; }
            *(float4*)&s_t[wid][c0] = t;
        }
        __syncwarp();

        float h = 0.f;
        if (lane < 30) {
            float z = s_bb[lane];
            #pragma unroll
            for (int k = 0; k < 30; k++) z += s_t[wid][k] * s_wb[k * 30 + lane];
            h = fmaxf(z, 0.f);
        }

        if (finalLayer) {
            float hv = (lane < 30) ? h : -1e30f;
            float mx = hv;
            #pragma unroll
            for (int o = 16; o > 0; o >>= 1) mx = fmaxf(mx, __shfl_xor_sync(0xffffffffu, mx, o));
            float ex = (lane < 30) ? expf(h - mx) : 0.f;
            float sm = ex;
            #pragma unroll
            for (int o = 16; o > 0; o >>= 1) sm += __shfl_xor_sync(0xffffffffu, sm, o);
            if (lane < 30) out[node * 30 + lane] = h - mx - logf(sm);
        } else {
            s_h[wid][lane] = (lane < 30) ? h : 0.f;
            __syncwarp();
            float yv = 0.f;
            if (lane < 30) {
                #pragma unroll
                for (int k = 0; k < 30; k++) yv += s_h[wid][k] * s_wa[k * 30 + lane];
            }
            yout[node * 32 + lane] = yv;   // lanes 30/31 write 0 padding
        }
        __syncwarp();   // protect s_t/s_h before next grid-stride iteration
    }
}

// ---------------- launch ----------------

extern "C" void kernel_launch(void* const* d_in, const int* in_sizes, int n_in,
                              void* d_out, int out_size) {
    const float* x   = (const float*)d_in[0];
    const int*   ei  = (const int*)d_in[1];
    const float* w1a = (const float*)d_in[2];
    const float* b1a = (const float*)d_in[3];
    const float* w1b = (const float*)d_in[4];
    const float* b1b = (const float*)d_in[5];
    const float* w2a = (const float*)d_in[6];
    const float* b2a = (const float*)d_in[7];
    const float* w2b = (const float*)d_in[8];
    const float* b2b = (const float*)d_in[9];
    const float* w3a = (const float*)d_in[10];
    const float* b3a = (const float*)d_in[11];
    const float* w3b = (const float*)d_in[12];
    const float* b3b = (const float*)d_in[13];
    float* out = (float*)d_out;

    int n = in_sizes[0] / 128;
    int E = in_sizes[1] / 2;

    int eb   = (E + 255) / 256;
    int nb1k = (n + 1023) / 1024;
    int nwb  = (n + 7) / 8;
    int lgrid = nwb < 1184 ? nwb : 1184;

    k_zero <<<nb1k, 1024>>>(n);
    k_count<<<eb, 256>>>(ei, E, n);
    k_alloc<<<nb1k, 1024>>>(n);
    k_fill <<<eb, 256>>>(ei, E, n);

    k_pre  <<<(n + 31) / 32, 256>>>(x, w1a, n);
    k_layer<<<lgrid, 256>>>(0, 0, b1a, w1b, b1b, w2a, nullptr, n);
    k_layer<<<lgrid, 256>>>(1, 0, b2a, w2b, b2b, w3a, nullptr, n);
    k_layer<<<lgrid, 256>>>(0, 1, b3a, w3b, b3b, nullptr, out, n);
}